// round 12
// baseline (speedup 1.0000x reference)
#include <cuda_runtime.h>
#include <cuda_bf16.h>

#define N_NODES  50000
#define N_GRAPHS 32
#define NODE_F   16
#define GLOBAL_F 2
#define HID      300
#define LAT      100
#define N_EDGES  800000
#define HP       304   // padded hidden (300 -> 304, float4-friendly)
#define LP       104   // padded LAT (100 -> 104)
#define TE       32    // edges per block in edge kernel

// ---------------- scratch (static device globals; no runtime alloc) -------------
__device__ __align__(16) float g_A[N_NODES * HP];   // A = x @ (Wt - Wb) + b1
__device__ __align__(16) float g_B[N_NODES * HP];   // B = x @ Wb
__device__ __align__(16) float g_S[N_NODES * LAT];  // scatter accumulator
__device__ __align__(16) float g_X1[N_NODES * LAT]; // node features between layers
__device__ int   g_deg[N_NODES];
__device__ int   g_gcnt[N_GRAPHS];
__device__ float g_pool[N_GRAPHS * LAT];
__device__ __align__(16) float g_W2p[HP * HP];      // zero-padded 300x300 -> 304x304
__device__ __align__(16) float g_b2p[HP];
__device__ __align__(16) float g_W3p[HP * LP];      // zero-padded 300x100 -> 304x104
__device__ __align__(16) float g_b3p[LP];

// ---------------- small utility kernels ------------------------------------------
__global__ void k_zero_misc() {
    int i = blockIdx.x * blockDim.x + threadIdx.x;
    if (i < N_NODES) g_deg[i] = 0;
    if (i < N_GRAPHS) g_gcnt[i] = 0;
    if (i < N_GRAPHS * LAT) g_pool[i] = 0.f;
}
__global__ void k_zeroS() {
    int i = blockIdx.x * blockDim.x + threadIdx.x;
    if (i < N_NODES * LAT) g_S[i] = 0.f;
}
__global__ void k_deg(const int* __restrict__ dst) {          // int32 indices!
    int i = blockIdx.x * blockDim.x + threadIdx.x;
    if (i < N_EDGES) atomicAdd(&g_deg[dst[i]], 1);
}
__global__ void k_gcnt(const int* __restrict__ batch) {       // int32 indices!
    int i = blockIdx.x * blockDim.x + threadIdx.x;
    if (i < N_NODES) atomicAdd(&g_gcnt[batch[i]], 1);
}
// pad weights: W2p[304x304], W3p[304x104], b2p, b3p
__global__ void k_padw(const float* __restrict__ w2, const float* __restrict__ b2,
                       const float* __restrict__ w3, const float* __restrict__ b3) {
    int i = blockIdx.x * blockDim.x + threadIdx.x;
    if (i < HP * HP) {
        int r = i / HP, c = i % HP;
        g_W2p[i] = (r < HID && c < HID) ? w2[r * HID + c] : 0.f;
    }
    if (i < HP * LP) {
        int r = i / LP, c = i % LP;
        g_W3p[i] = (r < HID && c < LAT) ? w3[r * LAT + c] : 0.f;
    }
    if (i < HP) g_b2p[i] = (i < HID) ? b2[i] : 0.f;
    if (i < LP) g_b3p[i] = (i < LAT) ? b3[i] : 0.f;
}

// ---------------- per-node pre-GEMM: A = x@(Wt-Wb)+b1, B = x@Wb ------------------
// FROM_X1 selects g_X1 (device symbol, referenced ONLY in device code) as input.
template <int IN, bool FROM_X1>
__global__ void k_pre(const float* __restrict__ xin, const float* __restrict__ w1,
                      const float* __restrict__ b1) {
    const float* x = FROM_X1 ? (const float*)g_X1 : xin;
    __shared__ float xs[16 * IN];
    int base = blockIdx.x * 16;   // N_NODES % 16 == 0
    for (int t = threadIdx.x; t < 16 * IN; t += blockDim.x)
        xs[t] = x[(base + t / IN) * IN + (t % IN)];
    __syncthreads();
    for (int o = threadIdx.x; o < 16 * HP; o += blockDim.x) {
        int nl = o / HP, c = o % HP;
        float accA = 0.f, accB = 0.f;
        if (c < HID) {
            accA = b1[c];
            const float* xr = &xs[nl * IN];
#pragma unroll 4
            for (int k = 0; k < IN; k++) {
                float xv = xr[k];
                float wt = w1[k * HID + c];
                float wb = w1[(IN + k) * HID + c];
                accB = fmaf(xv, wb, accB);
                accA = fmaf(xv, wt - wb, accA);
            }
        }
        int n = base + nl;
        g_A[n * HP + c] = accA;   // pads (c>=300) written as 0
        g_B[n * HP + c] = accB;
    }
}

// ---------------- fused edge kernel ----------------------------------------------
// sh holds h1 = relu(A[dst]+B[src]); h2 computed into regs, written back in-place;
// m = h2 @ W3p + b3 scattered via atomics. 32 edges/block, 8 warps x 4 edges.
__global__ void __launch_bounds__(256)
k_edge(const int* __restrict__ src, const int* __restrict__ dst) {
    __shared__ float sh[TE * HP];        // 38912 bytes
    __shared__ int s_dst[TE];
    __shared__ int s_src[TE];

    const int tid = threadIdx.x;
    const int e0 = blockIdx.x * TE;
    if (tid < TE) {
        s_src[tid] = src[e0 + tid];
        s_dst[tid] = dst[e0 + tid];
    }
    __syncthreads();

    // phase 0: gather + add + relu -> sh (full padded width; pads are zeros)
    for (int o = tid; o < TE * (HP / 4); o += 256) {
        int e = o / (HP / 4), q = (o % (HP / 4)) * 4;
        float4 a = *(const float4*)&g_A[s_dst[e] * HP + q];
        float4 b = *(const float4*)&g_B[s_src[e] * HP + q];
        float4 v;
        v.x = fmaxf(a.x + b.x, 0.f);
        v.y = fmaxf(a.y + b.y, 0.f);
        v.z = fmaxf(a.z + b.z, 0.f);
        v.w = fmaxf(a.w + b.w, 0.f);
        *(float4*)&sh[e * HP + q] = v;
    }
    __syncthreads();

    const int warp = tid >> 5, lane = tid & 31;
    const int eb = warp * 4;             // this warp's 4 edges

    // phase 1: h2 = relu(h1 @ W2p + b2) into registers (3 column passes)
    float h2r[3][16];                    // [pass][edge*4 + col]
#pragma unroll
    for (int ch = 0; ch < 3; ch++) {
        const int c0 = ch * 128 + lane * 4;
        float acc[16];
#pragma unroll
        for (int k = 0; k < 16; k++) acc[k] = 0.f;
        if (c0 < HP) {
            float4 bb = *(const float4*)&g_b2p[c0];
#pragma unroll
            for (int e = 0; e < 4; e++) {
                acc[e * 4 + 0] = bb.x; acc[e * 4 + 1] = bb.y;
                acc[e * 4 + 2] = bb.z; acc[e * 4 + 3] = bb.w;
            }
            for (int j = 0; j < HP; j += 4) {
                float4 h[4];
#pragma unroll
                for (int e = 0; e < 4; e++)
                    h[e] = *(const float4*)&sh[(eb + e) * HP + j];
                const float* wbase = &g_W2p[j * HP + c0];
#pragma unroll
                for (int jj = 0; jj < 4; jj++) {
                    float4 w = *(const float4*)&wbase[jj * HP];
#pragma unroll
                    for (int e = 0; e < 4; e++) {
                        float hv = (jj == 0) ? h[e].x : (jj == 1) ? h[e].y
                                 : (jj == 2) ? h[e].z : h[e].w;
                        acc[e * 4 + 0] = fmaf(hv, w.x, acc[e * 4 + 0]);
                        acc[e * 4 + 1] = fmaf(hv, w.y, acc[e * 4 + 1]);
                        acc[e * 4 + 2] = fmaf(hv, w.z, acc[e * 4 + 2]);
                        acc[e * 4 + 3] = fmaf(hv, w.w, acc[e * 4 + 3]);
                    }
                }
            }
        }
#pragma unroll
        for (int k = 0; k < 16; k++) h2r[ch][k] = fmaxf(acc[k], 0.f);
    }
    __syncwarp();   // all lanes done READING this warp's rows of sh

    // write h2 back in-place (each warp owns its 4 rows exclusively)
#pragma unroll
    for (int ch = 0; ch < 3; ch++) {
        const int c0 = ch * 128 + lane * 4;
        if (c0 < HP) {
#pragma unroll
            for (int e = 0; e < 4; e++) {
                float4 v = make_float4(h2r[ch][e * 4 + 0], h2r[ch][e * 4 + 1],
                                       h2r[ch][e * 4 + 2], h2r[ch][e * 4 + 3]);
                *(float4*)&sh[(eb + e) * HP + c0] = v;
            }
        }
    }
    __syncwarp();

    // phase 2: m = h2 @ W3p + b3, atomic scatter-add to S[dst]
    {
        const int c0 = lane * 4;         // lanes 0..25 active
        if (c0 < LP) {
            float acc[16];
            float4 bb = *(const float4*)&g_b3p[c0];
#pragma unroll
            for (int e = 0; e < 4; e++) {
                acc[e * 4 + 0] = bb.x; acc[e * 4 + 1] = bb.y;
                acc[e * 4 + 2] = bb.z; acc[e * 4 + 3] = bb.w;
            }
            for (int j = 0; j < HP; j += 4) {
                float4 h[4];
#pragma unroll
                for (int e = 0; e < 4; e++)
                    h[e] = *(const float4*)&sh[(eb + e) * HP + j];
                const float* wbase = &g_W3p[j * LP + c0];
#pragma unroll
                for (int jj = 0; jj < 4; jj++) {
                    float4 w = *(const float4*)&wbase[jj * LP];
#pragma unroll
                    for (int e = 0; e < 4; e++) {
                        float hv = (jj == 0) ? h[e].x : (jj == 1) ? h[e].y
                                 : (jj == 2) ? h[e].z : h[e].w;
                        acc[e * 4 + 0] = fmaf(hv, w.x, acc[e * 4 + 0]);
                        acc[e * 4 + 1] = fmaf(hv, w.y, acc[e * 4 + 1]);
                        acc[e * 4 + 2] = fmaf(hv, w.z, acc[e * 4 + 2]);
                        acc[e * 4 + 3] = fmaf(hv, w.w, acc[e * 4 + 3]);
                    }
                }
            }
            if (c0 < LAT) {   // cols c0..c0+3 all < 100 for lanes 0..24
#pragma unroll
                for (int e = 0; e < 4; e++) {
                    float* Sp = &g_S[s_dst[eb + e] * LAT + c0];
                    atomicAdd(Sp + 0, acc[e * 4 + 0]);
                    atomicAdd(Sp + 1, acc[e * 4 + 1]);
                    atomicAdd(Sp + 2, acc[e * 4 + 2]);
                    atomicAdd(Sp + 3, acc[e * 4 + 3]);
                }
            }
        }
    }
}

// ---------------- post kernels ----------------------------------------------------
__global__ void k_post0() {   // X1 = relu(S / max(deg,1))
    int i = blockIdx.x * blockDim.x + threadIdx.x;
    if (i < N_NODES * LAT) {
        int n = i / LAT;
        float d = (float)max(g_deg[n], 1);
        g_X1[i] = fmaxf(g_S[i] / d, 0.f);
    }
}
__global__ void k_post1(const int* __restrict__ batch) {  // + mean-pool accum
    int i = blockIdx.x * blockDim.x + threadIdx.x;
    if (i < N_NODES * LAT) {
        int n = i / LAT, c = i % LAT;
        float d = (float)max(g_deg[n], 1);
        float v = fmaxf(g_S[i] / d, 0.f);
        atomicAdd(&g_pool[batch[n] * LAT + c], v);
    }
}

// ---------------- final head: pool-mean | u -> 102 -> 100 -> 100 -> 1 -------------
__global__ void k_final(const float* __restrict__ u,
                        const float* __restrict__ w1, const float* __restrict__ b1,
                        const float* __restrict__ w2, const float* __restrict__ b2,
                        const float* __restrict__ w3, const float* __restrict__ b3,
                        float* __restrict__ out) {
    __shared__ float P[N_GRAPHS][LAT + GLOBAL_F];
    __shared__ float H1[N_GRAPHS][LAT];
    __shared__ float H2[N_GRAPHS][LAT];
    int tid = threadIdx.x;
    for (int o = tid; o < N_GRAPHS * LAT; o += blockDim.x) {
        int g = o / LAT, c = o % LAT;
        P[g][c] = g_pool[o] / fmaxf((float)g_gcnt[g], 1.f);
    }
    for (int o = tid; o < N_GRAPHS * GLOBAL_F; o += blockDim.x)
        P[o / GLOBAL_F][LAT + (o % GLOBAL_F)] = u[o];
    __syncthreads();
    for (int o = tid; o < N_GRAPHS * LAT; o += blockDim.x) {
        int g = o / LAT, c = o % LAT;
        float a = b1[c];
#pragma unroll 4
        for (int k = 0; k < LAT + GLOBAL_F; k++) a = fmaf(P[g][k], w1[k * LAT + c], a);
        H1[g][c] = fmaxf(a, 0.f);
    }
    __syncthreads();
    for (int o = tid; o < N_GRAPHS * LAT; o += blockDim.x) {
        int g = o / LAT, c = o % LAT;
        float a = b2[c];
#pragma unroll 4
        for (int k = 0; k < LAT; k++) a = fmaf(H1[g][k], w2[k * LAT + c], a);
        H2[g][c] = fmaxf(a, 0.f);
    }
    __syncthreads();
    for (int g = tid; g < N_GRAPHS; g += blockDim.x) {
        float a = b3[0];
#pragma unroll 4
        for (int k = 0; k < LAT; k++) a = fmaf(H2[g][k], w3[k], a);
        out[g] = a;
    }
}

// ---------------- launch ----------------------------------------------------------
extern "C" void kernel_launch(void* const* d_in, const int* in_sizes, int n_in,
                              void* d_out, int out_size) {
    const float* x      = (const float*)d_in[0];
    const int*   eidx   = (const int*)d_in[1];     // int32 (JAX x64 disabled!)
    const int*   batch  = (const int*)d_in[2];     // int32
    const float* u      = (const float*)d_in[3];
    const float* l0_w1 = (const float*)d_in[4];
    const float* l0_b1 = (const float*)d_in[5];
    const float* l0_w2 = (const float*)d_in[6];
    const float* l0_b2 = (const float*)d_in[7];
    const float* l0_w3 = (const float*)d_in[8];
    const float* l0_b3 = (const float*)d_in[9];
    const float* l1_w1 = (const float*)d_in[10];
    const float* l1_b1 = (const float*)d_in[11];
    const float* l1_w2 = (const float*)d_in[12];
    const float* l1_b2 = (const float*)d_in[13];
    const float* l1_w3 = (const float*)d_in[14];
    const float* l1_b3 = (const float*)d_in[15];
    const float* lin_w1 = (const float*)d_in[16];
    const float* lin_b1 = (const float*)d_in[17];
    const float* lin_w2 = (const float*)d_in[18];
    const float* lin_b2 = (const float*)d_in[19];
    const float* lin_w3 = (const float*)d_in[20];
    const float* lin_b3 = (const float*)d_in[21];

    const int* src = eidx;              // edge_index[0]
    const int* dst = eidx + N_EDGES;    // edge_index[1]

    // counts
    k_zero_misc<<<(N_NODES + 255) / 256, 256>>>();
    k_deg<<<(N_EDGES + 255) / 256, 256>>>(dst);
    k_gcnt<<<(N_NODES + 255) / 256, 256>>>(batch);

    // ---- layer 0 ----
    k_pre<NODE_F, false><<<N_NODES / 16, 256>>>(x, l0_w1, l0_b1);
    k_padw<<<(HP * HP + 255) / 256, 256>>>(l0_w2, l0_b2, l0_w3, l0_b3);
    k_zeroS<<<(N_NODES * LAT + 255) / 256, 256>>>();
    k_edge<<<N_EDGES / TE, 256>>>(src, dst);
    k_post0<<<(N_NODES * LAT + 255) / 256, 256>>>();

    // ---- layer 1 ----
    k_pre<LAT, true><<<N_NODES / 16, 256>>>(nullptr, l1_w1, l1_b1);
    k_padw<<<(HP * HP + 255) / 256, 256>>>(l1_w2, l1_b2, l1_w3, l1_b3);
    k_zeroS<<<(N_NODES * LAT + 255) / 256, 256>>>();
    k_edge<<<N_EDGES / TE, 256>>>(src, dst);
    k_post1<<<(N_NODES * LAT + 255) / 256, 256>>>(batch);

    // ---- head ----
    k_final<<<1, 256>>>(u, lin_w1, lin_b1, lin_w2, lin_b2, lin_w3, lin_b3,
                        (float*)d_out);
}